// round 4
// baseline (speedup 1.0000x reference)
#include <cuda_runtime.h>

// ---------------------------------------------------------------------------
// FraudQMLModel: logits = W * <Z0> + b, where <Z0> = state^H (U^H Z U) state,
// state = RX(x0)|0> kron RX(x1)|0>, U = constant 4x4 built from params.
// Collapsed form: <Z0> = sum_{p,q in {I,Z,Y}} C[p][q] f_p(x0) f_q(x1),
// f = (1, cos x, -sin x)  (single-qubit rho in the Pauli basis).
// Kernel 1 (1 thread): build U with clipping, reduce to 9 reals in g_C.
// Kernel 2 (bulk): 2 sincos + ~10 FMA per sample, DRAM-bound (12 B/sample).
// ---------------------------------------------------------------------------

struct Cx { float re, im; };

__device__ __forceinline__ Cx cmk(float r, float i) { Cx c; c.re = r; c.im = i; return c; }
__device__ __forceinline__ Cx cadd(Cx a, Cx b) { return cmk(a.re + b.re, a.im + b.im); }
__device__ __forceinline__ Cx cmul(Cx a, Cx b) {
    return cmk(a.re * b.re - a.im * b.im, a.re * b.im + a.im * b.re);
}
__device__ __forceinline__ Cx cscale(float s, Cx a) { return cmk(s * a.re, s * a.im); }
__device__ __forceinline__ Cx cconj(Cx a) { return cmk(a.re, -a.im); }
__device__ __forceinline__ Cx cexpi(float t) {
    float s, c;
    __sincosf(t, &s, &c);   // |t| <= 5 after clipping: abs err ~1e-6 vs 1e-3 gate
    return cmk(c, s);
}

// 9 reduced coefficients C[p][q], p for wire0, q for wire1; order {I, Z, Y}.
__device__ float g_C[9];

// ry(t) @ rz(r) 2x2
__device__ void ryrz(float t, float r, Cx m[2][2]) {
    float c, s;
    __sincosf(0.5f * t, &s, &c);
    Cx em = cexpi(-0.5f * r);
    Cx ep = cexpi(0.5f * r);
    m[0][0] = cscale(c, em);
    m[0][1] = cscale(-s, ep);
    m[1][0] = cscale(s, em);
    m[1][1] = cscale(c, ep);
}

__global__ void setup_kernel(const float* __restrict__ params, int L) {
    if (threadIdx.x != 0 || blockIdx.x != 0) return;

    // U = I
    Cx U[4][4];
    #pragma unroll
    for (int i = 0; i < 4; i++)
        #pragma unroll
        for (int j = 0; j < 4; j++)
            U[i][j] = cmk(i == j ? 1.0f : 0.0f, 0.0f);

    // A = (H kron H) @ CNOT = 0.5 * sA  (HH with columns 2,3 swapped)
    const float sA[4][4] = {
        { 1.f,  1.f,  1.f,  1.f},
        { 1.f, -1.f, -1.f,  1.f},
        { 1.f,  1.f, -1.f, -1.f},
        { 1.f, -1.f,  1.f, -1.f}
    };

    for (int l = 0; l < L; l++) {
        float p[14];
        #pragma unroll
        for (int i = 0; i < 14; i++) {
            float v = params[l * 14 + i];
            float lim = (i < 12) ? 5.0f : 1.0f;
            p[i] = fminf(fmaxf(v, -lim), lim);
        }

        // Combined diagonal of PhaseShift pair and RZ pair:
        // Pd[2j+k] = (j? e^{i p2} : 1) * (k? e^{i p3} : 1)
        // Sd[2j+k] = exp(i*((j? +a:-a)/2 + (k? +b:-b)/2)), a=p4+p6, b=p5+p7
        Cx e2 = cexpi(p[2]);
        Cx e3 = cexpi(p[3]);
        float a = p[4] + p[6];
        float bb = p[5] + p[7];
        Cx PS[4];
        #pragma unroll
        for (int j = 0; j < 2; j++)
            #pragma unroll
            for (int k = 0; k < 2; k++) {
                Cx Pd = cmk(1.0f, 0.0f);
                if (j) Pd = cmul(Pd, e2);
                if (k) Pd = cmul(Pd, e3);
                float ph = (j ? a : -a) * 0.5f + (k ? bb : -bb) * 0.5f;
                PS[2 * j + k] = cmul(Pd, cexpi(ph));
            }

        // X = diag(PS) @ (0.5*sA)
        Cx X[4][4];
        #pragma unroll
        for (int i = 0; i < 4; i++)
            #pragma unroll
            for (int j = 0; j < 4; j++)
                X[i][j] = cscale(0.5f * sA[i][j], PS[i]);

        // D = kron(ry(p10)@rz(p8), ry(p11)@rz(p9))
        Cx m0[2][2], m1[2][2];
        ryrz(p[10], p[8], m0);
        ryrz(p[11], p[9], m1);
        Cx D[4][4];
        #pragma unroll
        for (int j = 0; j < 2; j++)
            #pragma unroll
            for (int k = 0; k < 2; k++)
                #pragma unroll
                for (int lo = 0; lo < 2; lo++)
                    #pragma unroll
                    for (int m = 0; m < 2; m++)
                        D[2 * j + k][2 * lo + m] = cmul(m0[j][lo], m1[k][m]);

        // Lr = D @ X
        Cx Lr[4][4];
        #pragma unroll
        for (int i = 0; i < 4; i++)
            #pragma unroll
            for (int j = 0; j < 4; j++) {
                Cx acc = cmk(0.0f, 0.0f);
                #pragma unroll
                for (int k = 0; k < 4; k++)
                    acc = cadd(acc, cmul(D[i][k], X[k][j]));
                Lr[i][j] = acc;
            }

        // CPhase: scale row 3 by e^{i(p12+p13)}
        Cx cp = cexpi(p[12] + p[13]);
        #pragma unroll
        for (int j = 0; j < 4; j++)
            Lr[3][j] = cmul(cp, Lr[3][j]);

        // U = Lr @ U
        Cx Un[4][4];
        #pragma unroll
        for (int i = 0; i < 4; i++)
            #pragma unroll
            for (int j = 0; j < 4; j++) {
                Cx acc = cmk(0.0f, 0.0f);
                #pragma unroll
                for (int k = 0; k < 4; k++)
                    acc = cadd(acc, cmul(Lr[i][k], U[k][j]));
                Un[i][j] = acc;
            }
        #pragma unroll
        for (int i = 0; i < 4; i++)
            #pragma unroll
            for (int j = 0; j < 4; j++)
                U[i][j] = Un[i][j];
    }

    // M = U^H Z U,  Z = diag(1,1,-1,-1)
    const float zsgn[4] = {1.f, 1.f, -1.f, -1.f};
    Cx M[4][4];
    #pragma unroll
    for (int aI = 0; aI < 4; aI++)
        #pragma unroll
        for (int bI = 0; bI < 4; bI++) {
            Cx acc = cmk(0.0f, 0.0f);
            #pragma unroll
            for (int c = 0; c < 4; c++)
                acc = cadd(acc, cscale(zsgn[c], cmul(cconj(U[c][aI]), U[c][bI])));
            M[aI][bI] = acc;
        }

    // Pauli set {I, Z, Y}
    Cx Pm[3][2][2];
    Pm[0][0][0] = cmk(1, 0); Pm[0][0][1] = cmk(0, 0);
    Pm[0][1][0] = cmk(0, 0); Pm[0][1][1] = cmk(1, 0);
    Pm[1][0][0] = cmk(1, 0); Pm[1][0][1] = cmk(0, 0);
    Pm[1][1][0] = cmk(0, 0); Pm[1][1][1] = cmk(-1, 0);
    Pm[2][0][0] = cmk(0, 0); Pm[2][0][1] = cmk(0, -1);
    Pm[2][1][0] = cmk(0, 1); Pm[2][1][1] = cmk(0, 0);

    // C[p][q] = 0.25 * Re( sum P[p][j][l] P[q][k][m] M[2l+m][2j+k] )
    for (int pp = 0; pp < 3; pp++)
        for (int qq = 0; qq < 3; qq++) {
            Cx acc = cmk(0.0f, 0.0f);
            #pragma unroll
            for (int j = 0; j < 2; j++)
                #pragma unroll
                for (int lo = 0; lo < 2; lo++)
                    #pragma unroll
                    for (int k = 0; k < 2; k++)
                        #pragma unroll
                        for (int m = 0; m < 2; m++)
                            acc = cadd(acc, cmul(cmul(Pm[pp][j][lo], Pm[qq][k][m]),
                                                 M[2 * lo + m][2 * j + k]));
            g_C[pp * 3 + qq] = 0.25f * acc.re;
        }
}

// Fast-intrinsic eval: __sincosf is MUFU-backed (abs err ~1e-6 for small |x|,
// inputs are N(0,1)) — keeps the bulk kernel DRAM-bound, not compute-bound.
__device__ __forceinline__ float eval_z(float x0, float x1, const float C[9]) {
    float s0, c0, s1, c1;
    __sincosf(x0, &s0, &c0);
    __sincosf(x1, &s1, &c1);
    // f0 = (1, c0, -s0), f1 = (1, c1, -s1)
    float r0 = fmaf(C[1], c1, C[0]) - C[2] * s1;
    float r1 = fmaf(C[4], c1, C[3]) - C[5] * s1;
    float r2 = fmaf(C[7], c1, C[6]) - C[8] * s1;
    return fmaf(c0, r1, r0) - s0 * r2;
}

// 4 samples per thread: 2x LDG.128 + 1x STG.128 (nc==1 fast path).
__global__ void __launch_bounds__(256) apply_kernel4(
        const float* __restrict__ x,
        const float* __restrict__ W,
        const float* __restrict__ bvec,
        float* __restrict__ out,
        int nquads) {  // nquads = B/4 (B divisible by 4 on this path)
    int t = blockIdx.x * blockDim.x + threadIdx.x;
    if (t >= nquads) return;

    float C[9];
    #pragma unroll
    for (int i = 0; i < 9; i++) C[i] = g_C[i];

    const float4* xv = reinterpret_cast<const float4*>(x);
    float4 v0 = __ldg(xv + 2 * t);
    float4 v1 = __ldg(xv + 2 * t + 1);

    float w0 = __ldg(W);
    float b0 = __ldg(bvec);

    float4 o;
    o.x = fmaf(w0, eval_z(v0.x, v0.y, C), b0);
    o.y = fmaf(w0, eval_z(v0.z, v0.w, C), b0);
    o.z = fmaf(w0, eval_z(v1.x, v1.y, C), b0);
    o.w = fmaf(w0, eval_z(v1.z, v1.w, C), b0);
    reinterpret_cast<float4*>(out)[t] = o;
}

// Generic fallback (any B, any nc): 1 sample per thread.
__global__ void __launch_bounds__(256) apply_kernel_gen(
        const float* __restrict__ x,
        const float* __restrict__ W,
        const float* __restrict__ bvec,
        float* __restrict__ out,
        int B, int nc) {
    int i = blockIdx.x * blockDim.x + threadIdx.x;
    if (i >= B) return;
    float C[9];
    #pragma unroll
    for (int k = 0; k < 9; k++) C[k] = g_C[k];
    float z = eval_z(x[2 * i], x[2 * i + 1], C);
    for (int c = 0; c < nc; c++)
        out[i * nc + c] = fmaf(__ldg(W + c), z, __ldg(bvec + c));
}

extern "C" void kernel_launch(void* const* d_in, const int* in_sizes, int n_in,
                              void* d_out, int out_size) {
    const float* x = (const float*)d_in[0];
    const float* params = (const float*)d_in[1];
    const float* W = (const float*)d_in[2];
    const float* b = (const float*)d_in[3];
    float* out = (float*)d_out;

    int B = in_sizes[0] / 2;
    int L = in_sizes[1] / 14;
    int nc = in_sizes[3];

    setup_kernel<<<1, 1>>>(params, L);

    if (nc == 1 && (B % 4) == 0) {
        int nquads = B / 4;                 // 1,048,576 threads for B=4.19M
        int block = 256;
        int grid = (nquads + block - 1) / block;
        apply_kernel4<<<grid, block>>>(x, W, b, out, nquads);
    } else {
        int block = 256;
        int grid = (B + block - 1) / block;
        apply_kernel_gen<<<grid, block>>>(x, W, b, out, B, nc);
    }
}